// round 7
// baseline (speedup 1.0000x reference)
#include <cuda_runtime.h>
#include <cstdint>

#define N_NODES_MAX 100000
#define N_EDGES_MAX 600000

// Scratch (device globals)
__device__ __align__(16) float g_xsum[(size_t)N_NODES_MAX * 128];  // mean-agg; reused as 'a'
__device__ __align__(16) float g_h1  [(size_t)N_NODES_MAX * 128];  // layer-1 out; reused as 'b'
__device__ __align__(16) float g_h2  [(size_t)N_NODES_MAX * 128];  // layer-2 out
__device__ __align__(16) float g_eagg[(size_t)N_NODES_MAX * 32];   // mean of edge_attr per dst
__device__ __align__(16) float g_degc[N_NODES_MAX];                // deg>0 ? 1 : 0
__device__ __align__(16) float g_P   [2 * 32 * 128];               // We_l @ Wl_l
__device__ __align__(16) float g_bv1 [2 * 128];                    // be_l @ Wl_l
__device__ __align__(16) float g_bv0 [2 * 128];                    // bl_l + br_l
// CSR (built per launch)
__device__ int g_rowptr[N_NODES_MAX + 1];
__device__ int g_cnt   [N_NODES_MAX];
__device__ int g_bsum  [1024];
__device__ int g_boff  [1024];
__device__ int g_csr_src[N_EDGES_MAX];
__device__ int g_csr_eid[N_EDGES_MAX];

// ---------------------------------------------------------------------------
__device__ __forceinline__ uint32_t to_tf32(float v) {
    uint32_t u;
    asm("cvt.rna.tf32.f32 %0, %1;" : "=r"(u) : "f"(v));
    return u;
}
__device__ __forceinline__ void mma_tf32(float c[4], const uint32_t a[4],
                                         uint32_t b0, uint32_t b1) {
    asm("mma.sync.aligned.m16n8k8.row.col.f32.tf32.tf32.f32 "
        "{%0,%1,%2,%3}, {%4,%5,%6,%7}, {%8,%9}, {%0,%1,%2,%3};"
        : "+f"(c[0]), "+f"(c[1]), "+f"(c[2]), "+f"(c[3])
        : "r"(a[0]), "r"(a[1]), "r"(a[2]), "r"(a[3]), "r"(b0), "r"(b1));
}

// ---------------------------------------------------------------------------
// CSR build
// ---------------------------------------------------------------------------
__global__ void k_zero_int(int* __restrict__ p, int n) {
    int i = blockIdx.x * blockDim.x + threadIdx.x;
    if (i < n) p[i] = 0;
}

__global__ void k_hist(const int* __restrict__ ei, int* __restrict__ cnt, int E, int N) {
    int e = blockIdx.x * blockDim.x + threadIdx.x;
    if (e < E) {
        int d = ei[E + e];
        if ((unsigned)d < (unsigned)N) atomicAdd(&cnt[d], 1);
    }
}

__global__ void k_scan1(const int* __restrict__ cnt, int* __restrict__ rowptr,
                        int* __restrict__ bsum, int N) {
    __shared__ int sm[512];
    int t = threadIdx.x, b = blockIdx.x, i = b * 512 + t;
    int v = (i < N) ? cnt[i] : 0;
    sm[t] = v;
    __syncthreads();
    #pragma unroll
    for (int off = 1; off < 512; off <<= 1) {
        int add = (t >= off) ? sm[t - off] : 0;
        __syncthreads();
        sm[t] += add;
        __syncthreads();
    }
    if (i < N) rowptr[i + 1] = sm[t];
    if (t == 511) bsum[b] = sm[511];
}

__global__ void k_scan2(const int* __restrict__ bsum, int* __restrict__ boff, int nb) {
    __shared__ int sm[1024];
    int t = threadIdx.x;
    sm[t] = (t < nb) ? bsum[t] : 0;
    __syncthreads();
    #pragma unroll
    for (int off = 1; off < 1024; off <<= 1) {
        int add = (t >= off) ? sm[t - off] : 0;
        __syncthreads();
        sm[t] += add;
        __syncthreads();
    }
    if (t < nb) boff[t] = (t == 0) ? 0 : sm[t - 1];
}

// add block offsets; degc from cnt; zero cnt (reused as fill cursor)
__global__ void k_scan3(int* __restrict__ rowptr, const int* __restrict__ boff,
                        int* __restrict__ cnt, float* __restrict__ degc, int N) {
    int t = threadIdx.x, b = blockIdx.x, i = b * 512 + t;
    if (i < N) {
        rowptr[i + 1] += boff[b];
        degc[i] = cnt[i] > 0 ? 1.f : 0.f;
        cnt[i] = 0;
        if (i == 0) rowptr[0] = 0;
    }
}

__global__ void k_fill(const int* __restrict__ ei, const int* __restrict__ rowptr,
                       int* __restrict__ cnt, int* __restrict__ csr_src,
                       int* __restrict__ csr_eid, int E, int N) {
    int e = blockIdx.x * blockDim.x + threadIdx.x;
    if (e < E) {
        int s = ei[e];
        int d = ei[E + e];
        if ((unsigned)d < (unsigned)N) {
            int pos = rowptr[d] + atomicAdd(&cnt[d], 1);
            csr_src[pos] = s;
            csr_eid[pos] = e;
        }
    }
}

// ---------------------------------------------------------------------------
// CSR aggregation: one warp per node, register accumulate, MEAN written
// (inv-degree folded in here). Layer 1 also sums edge_attr (eagg, mean).
// ---------------------------------------------------------------------------
__global__ void k_agg_l1(const float* __restrict__ x, const float* __restrict__ ea,
                         const int* __restrict__ rowptr,
                         const int* __restrict__ csr_src, const int* __restrict__ csr_eid,
                         float* __restrict__ xsum, float* __restrict__ eagg, int N) {
    int lane = threadIdx.x & 31;
    int n = (blockIdx.x * blockDim.x + threadIdx.x) >> 5;
    if (n >= N) return;
    int beg = rowptr[n], end = rowptr[n + 1];
    float inv = 1.f / fmaxf((float)(end - beg), 1.f);
    const float4* x4 = (const float4*)x;
    float4 acc = make_float4(0.f, 0.f, 0.f, 0.f);
    float eacc = 0.f;
    int i = beg;
    for (; i + 1 < end; i += 2) {
        int s0 = __ldg(&csr_src[i]),     e0 = __ldg(&csr_eid[i]);
        int s1 = __ldg(&csr_src[i + 1]), e1 = __ldg(&csr_eid[i + 1]);
        float4 v0 = __ldg(x4 + (size_t)s0 * 32 + lane);
        float4 v1 = __ldg(x4 + (size_t)s1 * 32 + lane);
        float w0 = __ldg(&ea[(size_t)e0 * 32 + lane]);
        float w1 = __ldg(&ea[(size_t)e1 * 32 + lane]);
        acc.x += v0.x + v1.x; acc.y += v0.y + v1.y;
        acc.z += v0.z + v1.z; acc.w += v0.w + v1.w;
        eacc += w0 + w1;
    }
    if (i < end) {
        int s0 = __ldg(&csr_src[i]), e0 = __ldg(&csr_eid[i]);
        float4 v0 = __ldg(x4 + (size_t)s0 * 32 + lane);
        float w0 = __ldg(&ea[(size_t)e0 * 32 + lane]);
        acc.x += v0.x; acc.y += v0.y; acc.z += v0.z; acc.w += v0.w;
        eacc += w0;
    }
    acc.x *= inv; acc.y *= inv; acc.z *= inv; acc.w *= inv;
    ((float4*)xsum)[(size_t)n * 32 + lane] = acc;
    eagg[(size_t)n * 32 + lane] = eacc * inv;
}

__global__ void k_agg_l2(const float* __restrict__ x,
                         const int* __restrict__ rowptr,
                         const int* __restrict__ csr_src,
                         float* __restrict__ xsum, int N) {
    int lane = threadIdx.x & 31;
    int n = (blockIdx.x * blockDim.x + threadIdx.x) >> 5;
    if (n >= N) return;
    int beg = rowptr[n], end = rowptr[n + 1];
    float inv = 1.f / fmaxf((float)(end - beg), 1.f);
    const float4* x4 = (const float4*)x;
    float4 acc = make_float4(0.f, 0.f, 0.f, 0.f);
    int i = beg;
    for (; i + 1 < end; i += 2) {
        int s0 = __ldg(&csr_src[i]);
        int s1 = __ldg(&csr_src[i + 1]);
        float4 v0 = __ldg(x4 + (size_t)s0 * 32 + lane);
        float4 v1 = __ldg(x4 + (size_t)s1 * 32 + lane);
        acc.x += v0.x + v1.x; acc.y += v0.y + v1.y;
        acc.z += v0.z + v1.z; acc.w += v0.w + v1.w;
    }
    if (i < end) {
        int s0 = __ldg(&csr_src[i]);
        float4 v0 = __ldg(x4 + (size_t)s0 * 32 + lane);
        acc.x += v0.x; acc.y += v0.y; acc.z += v0.z; acc.w += v0.w;
    }
    acc.x *= inv; acc.y *= inv; acc.z *= inv; acc.w *= inv;
    ((float4*)xsum)[(size_t)n * 32 + lane] = acc;
}

// ---------------------------------------------------------------------------
// Precompute P_l = We_l @ Wl_l, bv1_l = be_l @ Wl_l, bv0_l = bl_l + br_l.
// ---------------------------------------------------------------------------
__global__ void k_precompute(const float* We1, const float* be1, const float* Wl1,
                             const float* bl1, const float* br1,
                             const float* We2, const float* be2, const float* Wl2,
                             const float* bl2, const float* br2,
                             float* P, float* bv1, float* bv0) {
    int l = blockIdx.x;
    int j = threadIdx.x;
    const float* We = l ? We2 : We1;
    const float* be = l ? be2 : be1;
    const float* Wl = l ? Wl2 : Wl1;
    const float* bl = l ? bl2 : bl1;
    const float* br = l ? br2 : br1;

    for (int i = 0; i < 32; i++) {
        float acc = 0.f;
        for (int k = 0; k < 128; k++) acc = fmaf(We[i * 128 + k], Wl[k * 128 + j], acc);
        P[l * 4096 + i * 128 + j] = acc;
    }
    float a1 = 0.f;
    for (int k = 0; k < 128; k++) a1 = fmaf(be[k], Wl[k * 128 + j], a1);
    bv1[l * 128 + j] = a1;
    bv0[l * 128 + j] = bl[j] + br[j];
}

// ---------------------------------------------------------------------------
// Tensor-core SAGE node GEMM (tf32 mma.sync m16n8k8), double-buffered,
// conflict-free fragment layouts:
//   C = act( A1 @ W1 + (A2 @ P)? + (B @ W2)? + bv0? + degc[m]*bv1? )
// (inv-degree already folded into A1/A2 by the aggregation kernels.)
// BM=128, BN=128, BK=16. 256 threads = 8 warps in 4x2; warp = 32x64.
// blockIdx.y==1 selects the alternate (W1q, bv0q, Cq) problem (predictor b).
// ---------------------------------------------------------------------------
__global__ __launch_bounds__(256, 2)
void k_gemm_sage_tc(const float* __restrict__ A1,
                    const float* __restrict__ A2,
                    const float* __restrict__ B,
                    const float* __restrict__ W1,
                    const float* __restrict__ P,
                    const float* __restrict__ W2,
                    const float* __restrict__ bv0,
                    const float* __restrict__ bv1,
                    const float* __restrict__ degc,
                    float* __restrict__ C,
                    const float* __restrict__ W1q,
                    const float* __restrict__ bv0q,
                    float* __restrict__ Cq,
                    int M, int relu) {
    __shared__ uint32_t As[2][128][20];   // [m][k], stride 20 -> conflict-free a-frags
    __shared__ uint32_t Ws[2][16][129];   // [k][n], stride 129 -> conflict-free b-frags

    if (blockIdx.y == 1) { W1 = W1q; bv0 = bv0q; C = Cq; }

    const int tid    = threadIdx.x;
    const int lane   = tid & 31;
    const int warp   = tid >> 5;
    const int gid    = lane >> 2;
    const int qid    = lane & 3;
    const int warp_m = warp >> 1;
    const int warp_n = warp & 1;
    const int m0     = blockIdx.x * 128;

    float c[2][8][4];
    #pragma unroll
    for (int mt = 0; mt < 2; mt++)
        #pragma unroll
        for (int nt = 0; nt < 8; nt++)
            #pragma unroll
            for (int i = 0; i < 4; i++) c[mt][nt][i] = 0.f;

    const int ktiles = (A2 != nullptr) ? 18 : 8;

    float ar[8], wr[8];

    // tile loader: global -> regs
    auto load_regs = [&](int kt) {
        const float* Ain;
        const float* Win;
        int kb, astride;
        if (kt < 8)       { Ain = A1; Win = W1; kb = kt * 16;        astride = 128; }
        else if (kt < 10) { Ain = A2; Win = P;  kb = (kt - 8) * 16;  astride = 32;  }
        else              { Ain = B;  Win = W2; kb = (kt - 10) * 16; astride = 128; }
        #pragma unroll
        for (int i = 0; i < 8; i++) {
            int lin = tid + i * 256;
            int m = lin >> 4;
            int k = lin & 15;
            int gm = m0 + m;
            ar[i] = (gm < M) ? Ain[(size_t)gm * astride + kb + k] : 0.f;
        }
        #pragma unroll
        for (int i = 0; i < 8; i++) {
            int lin = tid + i * 256;
            int k = lin >> 7;
            int j = lin & 127;
            wr[i] = Win[(size_t)(kb + k) * 128 + j];
        }
    };
    auto store_regs = [&](int buf) {
        #pragma unroll
        for (int i = 0; i < 8; i++) {
            int lin = tid + i * 256;
            As[buf][lin >> 4][lin & 15] = to_tf32(ar[i]);
        }
        #pragma unroll
        for (int i = 0; i < 8; i++) {
            int lin = tid + i * 256;
            Ws[buf][lin >> 7][lin & 127] = to_tf32(wr[i]);
        }
    };

    load_regs(0);
    store_regs(0);
    __syncthreads();
    int buf = 0;

    for (int kt = 0; kt < ktiles; kt++) {
        const bool has_next = (kt + 1 < ktiles);
        if (has_next) load_regs(kt + 1);     // LDG overlaps mma below

        #pragma unroll
        for (int ks = 0; ks < 2; ks++) {
            const int k8 = ks * 8;
            uint32_t a[2][4];
            #pragma unroll
            for (int mt = 0; mt < 2; mt++) {
                int row = warp_m * 32 + mt * 16 + gid;
                a[mt][0] = As[buf][row][k8 + qid];
                a[mt][1] = As[buf][row + 8][k8 + qid];
                a[mt][2] = As[buf][row][k8 + qid + 4];
                a[mt][3] = As[buf][row + 8][k8 + qid + 4];
            }
            #pragma unroll
            for (int nt = 0; nt < 8; nt++) {
                int col = warp_n * 64 + nt * 8 + gid;
                uint32_t b0 = Ws[buf][k8 + qid][col];
                uint32_t b1 = Ws[buf][k8 + qid + 4][col];
                mma_tf32(c[0][nt], a[0], b0, b1);
                mma_tf32(c[1][nt], a[1], b0, b1);
            }
        }

        if (has_next) store_regs(buf ^ 1);
        __syncthreads();
        buf ^= 1;
    }

    #pragma unroll
    for (int mt = 0; mt < 2; mt++) {
        int rbase = m0 + warp_m * 32 + mt * 16 + gid;
        #pragma unroll
        for (int h = 0; h < 2; h++) {
            int r = rbase + h * 8;
            if (r >= M) continue;
            float coef = (bv1 && degc) ? degc[r] : 0.f;
            #pragma unroll
            for (int nt = 0; nt < 8; nt++) {
                int j = warp_n * 64 + nt * 8 + qid * 2;
                float v0 = c[mt][nt][h * 2 + 0];
                float v1 = c[mt][nt][h * 2 + 1];
                if (bv0) { v0 += bv0[j]; v1 += bv0[j + 1]; }
                if (bv1) { v0 += coef * bv1[j]; v1 += coef * bv1[j + 1]; }
                if (relu) { v0 = fmaxf(v0, 0.f); v1 = fmaxf(v1, 0.f); }
                *(float2*)&C[(size_t)r * 128 + j] = make_float2(v0, v1);
            }
        }
    }
}

// ---------------------------------------------------------------------------
// Final edge predictor: out[e] = relu(a[src] + b[dst]) @ Wp2 + bp2
// ---------------------------------------------------------------------------
__global__ void k_edge_final(const float* __restrict__ a,
                             const float* __restrict__ b,
                             const int* __restrict__ ei,
                             const float* __restrict__ Wp2,
                             const float* __restrict__ bp2,
                             float* __restrict__ out,
                             int E, int N) {
    int lane = threadIdx.x & 31;
    int warp = (blockIdx.x * blockDim.x + threadIdx.x) >> 5;
    int nwarp = (gridDim.x * blockDim.x) >> 5;

    float4 w01 = ((const float4*)Wp2)[lane * 2];
    float4 w23 = ((const float4*)Wp2)[lane * 2 + 1];
    float b0 = bp2[0], b1 = bp2[1];

    for (int e = warp; e < E; e += nwarp) {
        int s = ei[e];
        int d = ei[E + e];
        if ((unsigned)s >= (unsigned)N || (unsigned)d >= (unsigned)N) continue;
        float4 av = __ldg((const float4*)a + (size_t)s * 32 + lane);
        float4 bv = __ldg((const float4*)b + (size_t)d * 32 + lane);
        float z0 = fmaxf(av.x + bv.x, 0.f);
        float z1 = fmaxf(av.y + bv.y, 0.f);
        float z2 = fmaxf(av.z + bv.z, 0.f);
        float z3 = fmaxf(av.w + bv.w, 0.f);
        float o0 = z0 * w01.x + z1 * w01.z + z2 * w23.x + z3 * w23.z;
        float o1 = z0 * w01.y + z1 * w01.w + z2 * w23.y + z3 * w23.w;
        #pragma unroll
        for (int off = 16; off > 0; off >>= 1) {
            o0 += __shfl_xor_sync(0xffffffffu, o0, off);
            o1 += __shfl_xor_sync(0xffffffffu, o1, off);
        }
        if (lane == 0) {
            float2 r = make_float2(o0 + b0, o1 + b1);
            *(float2*)&out[(size_t)e * 2] = r;
        }
    }
}

// ---------------------------------------------------------------------------
extern "C" void kernel_launch(void* const* d_in, const int* in_sizes, int n_in,
                              void* d_out, int out_size) {
    const float* x    = (const float*)d_in[0];
    const int*   ei   = (const int*)d_in[1];     // int32
    const float* ea   = (const float*)d_in[2];
    const float* We1  = (const float*)d_in[3];
    const float* be1  = (const float*)d_in[4];
    const float* Wl1  = (const float*)d_in[5];
    const float* bl1  = (const float*)d_in[6];
    const float* Wr1  = (const float*)d_in[7];
    const float* br1  = (const float*)d_in[8];
    const float* We2  = (const float*)d_in[9];
    const float* be2  = (const float*)d_in[10];
    const float* Wl2  = (const float*)d_in[11];
    const float* bl2  = (const float*)d_in[12];
    const float* Wr2  = (const float*)d_in[13];
    const float* br2  = (const float*)d_in[14];
    const float* Wp1  = (const float*)d_in[15];
    const float* bp1  = (const float*)d_in[16];
    const float* Wp2  = (const float*)d_in[17];
    const float* bp2  = (const float*)d_in[18];
    float*       out  = (float*)d_out;

    const int N = in_sizes[0] / 128;
    const int E = in_sizes[2] / 32;

    float *xsum, *h1, *h2, *eagg, *degc, *P, *bv1, *bv0;
    int *rowptr, *cnt, *bsum, *boff, *csr_src, *csr_eid;
    cudaGetSymbolAddress((void**)&xsum, g_xsum);
    cudaGetSymbolAddress((void**)&h1,   g_h1);
    cudaGetSymbolAddress((void**)&h2,   g_h2);
    cudaGetSymbolAddress((void**)&eagg, g_eagg);
    cudaGetSymbolAddress((void**)&degc, g_degc);
    cudaGetSymbolAddress((void**)&P,    g_P);
    cudaGetSymbolAddress((void**)&bv1,  g_bv1);
    cudaGetSymbolAddress((void**)&bv0,  g_bv0);
    cudaGetSymbolAddress((void**)&rowptr, g_rowptr);
    cudaGetSymbolAddress((void**)&cnt,    g_cnt);
    cudaGetSymbolAddress((void**)&bsum,   g_bsum);
    cudaGetSymbolAddress((void**)&boff,   g_boff);
    cudaGetSymbolAddress((void**)&csr_src, g_csr_src);
    cudaGetSymbolAddress((void**)&csr_eid, g_csr_eid);

    const int nb    = (N + 511) / 512;
    const int agrid = (N + 7) / 8;
    const int egrid = 2368;
    dim3 ggrid1((N + 127) / 128, 1);
    dim3 ggrid2((N + 127) / 128, 2);

    // ---- CSR build ----
    k_zero_int<<<(N + 255) / 256, 256>>>(cnt, N);
    k_hist<<<(E + 255) / 256, 256>>>(ei, cnt, E, N);
    k_scan1<<<nb, 512>>>(cnt, rowptr, bsum, N);
    k_scan2<<<1, 1024>>>(bsum, boff, nb);
    k_scan3<<<nb, 512>>>(rowptr, boff, cnt, degc, N);
    k_fill<<<(E + 255) / 256, 256>>>(ei, rowptr, cnt, csr_src, csr_eid, E, N);

    // weight precompute
    k_precompute<<<2, 128>>>(We1, be1, Wl1, bl1, br1, We2, be2, Wl2, bl2, br2, P, bv1, bv0);

    // ---- layer 1 ----
    k_agg_l1<<<agrid, 256>>>(x, ea, rowptr, csr_src, csr_eid, xsum, eagg, N);
    k_gemm_sage_tc<<<ggrid1, 256>>>(xsum, eagg, x, Wl1, P, Wr1,
                                    bv0, bv1, degc, h1,
                                    nullptr, nullptr, nullptr, N, 1);

    // ---- layer 2 ----
    k_agg_l2<<<agrid, 256>>>(h1, rowptr, csr_src, xsum, N);
    k_gemm_sage_tc<<<ggrid1, 256>>>(xsum, eagg, h1, Wl2, P + 4096, Wr2,
                                    bv0 + 128, bv1 + 128, degc, h2,
                                    nullptr, nullptr, nullptr, N, 1);

    // ---- edge predictor (factored): y=0 -> a=h2@Wp1[:128]+bp1 into xsum,
    //                                 y=1 -> b=h2@Wp1[128:] into h1
    k_gemm_sage_tc<<<ggrid2, 256>>>(h2, nullptr, nullptr, Wp1, nullptr, nullptr,
                                    bp1, nullptr, nullptr, xsum,
                                    Wp1 + 128 * 128, nullptr, h1, N, 0);

    k_edge_final<<<egrid, 256>>>(xsum, h1, ei, Wp2, bp2, out, E, N);
}